// round 13
// baseline (speedup 1.0000x reference)
#include <cuda_runtime.h>

#define BATCH 8
#define CD 256
#define CS 512
#define MPTS 4096
#define SPTS 1024
#define NPTS 4096
#define WLD 768

typedef unsigned int u32;

// ---------------- scratch (device globals) -----------------------------------
__device__ float g_z[BATCH * CD * SPTS];          // W2 @ sparse : [b][o][s]
__device__ float g_y[(size_t)BATCH * CD * MPTS];  // pre-BN y    : [b][o][m]
__device__ int   g_ki0[BATCH * MPTS];
__device__ int   g_ki1[BATCH * MPTS];
__device__ int   g_ki2[BATCH * MPTS];
__device__ float g_kw0[BATCH * MPTS];
__device__ float g_kw1[BATCH * MPTS];
__device__ float g_kw2[BATCH * MPTS];
__device__ float g_rsum[BATCH * CD];
__device__ float g_rsum2[BATCH * CD];

__device__ __forceinline__ float tf32rn(float x) {
    float y;
    asm("cvt.rna.tf32.f32 %0, %1;" : "=f"(y) : "f"(x));
    return y;
}

// ---------------- kernel 1: KNN (exact fp32, bit-matches reference) -----------
__global__ __launch_bounds__(256) void knn_kernel(
    const float* __restrict__ pcd,
    const int* __restrict__ dense_idx,
    const int* __restrict__ sparse_idx)
{
    __shared__ float sx[SPTS], sy[SPTS], sz[SPTS], ss[SPTS];
    const int b = blockIdx.y;
    const float* pb = pcd + (size_t)b * 3 * NPTS;

    for (int s = threadIdx.x; s < SPTS; s += blockDim.x) {
        int si = sparse_idx[b * SPTS + s];
        float x = pb[si], y = pb[NPTS + si], z = pb[2 * NPTS + si];
        ss[s] = __fadd_rn(__fadd_rn(__fmul_rn(x, x), __fmul_rn(y, y)), __fmul_rn(z, z));
        sx[s] = x; sy[s] = y; sz[s] = z;
    }
    __syncthreads();

    const int m = blockIdx.x * blockDim.x + threadIdx.x;
    const int di = dense_idx[b * MPTS + m];
    const float dx = pb[di], dy = pb[NPTS + di], dz = pb[2 * NPTS + di];
    const float dd = __fadd_rn(__fadd_rn(__fmul_rn(dx, dx), __fmul_rn(dy, dy)),
                               __fmul_rn(dz, dz));

    float d0 = 3.4e38f, d1 = 3.4e38f, d2v = 3.4e38f;
    int i0 = 0, i1 = 0, i2 = 0;
    #pragma unroll 4
    for (int s = 0; s < SPTS; s++) {
        float p0 = __fmul_rn(dx, sx[s]);
        float p1 = __fmul_rn(dy, sy[s]);
        float p2 = __fmul_rn(dz, sz[s]);
        float dot = __fadd_rn(__fadd_rn(p0, p1), p2);
        float d2 = __fadd_rn(__fadd_rn(dd, ss[s]), -__fmul_rn(2.0f, dot));
        if (d2 < d0)       { d2v = d1; i2 = i1; d1 = d0; i1 = i0; d0 = d2; i0 = s; }
        else if (d2 < d1)  { d2v = d1; i2 = i1; d1 = d2; i1 = s; }
        else if (d2 < d2v) { d2v = d2; i2 = s; }
    }
    float w0 = __fdiv_rn(1.0f, __fadd_rn(d0,  1e-8f));
    float w1 = __fdiv_rn(1.0f, __fadd_rn(d1,  1e-8f));
    float w2 = __fdiv_rn(1.0f, __fadd_rn(d2v, 1e-8f));
    float sum = __fadd_rn(__fadd_rn(w0, w1), w2);
    int gi = b * MPTS + m;
    g_ki0[gi] = i0; g_ki1[gi] = i1; g_ki2[gi] = i2;
    g_kw0[gi] = __fdiv_rn(w0, sum);
    g_kw1[gi] = __fdiv_rn(w1, sum);
    g_kw2[gi] = __fdiv_rn(w2, sum);
}

// ---------------- merged tf32 mma.sync GEMM (z + y in one launch) --------------
#define BKK 32
#define APAD 36
#define BPAD 136
#define NZBLK 128

__global__ __launch_bounds__(256, 2) void gemm_mma_all(
    const float* __restrict__ conv_w,
    const float* __restrict__ dense_data,
    const float* __restrict__ sparse_data,
    float* __restrict__ gy, float* __restrict__ gz)
{
    __shared__ float Asm[128 * APAD];
    __shared__ float Bsm[BKK * BPAD];

    const int flat = blockIdx.x;
    const bool isZ = flat < NZBLK;

    int KDIM, WOFF, LDXV, ldc, mtiles, idx;
    const float* Xbase; float* outp;
    if (isZ) { KDIM = CS; WOFF = CD; LDXV = SPTS; ldc = SPTS; mtiles = 8;
               Xbase = sparse_data; outp = gz; idx = flat; }
    else     { KDIM = CD; WOFF = 0;  LDXV = MPTS; ldc = MPTS; mtiles = 32;
               Xbase = dense_data; outp = gy; idx = flat - NZBLK; }

    const int mtile = idx % mtiles;
    const int otile = (idx / mtiles) & 1;
    const int b     = idx / (mtiles * 2);
    const int m0 = mtile * 128;
    const int o0 = otile * 128;
    const float* X = Xbase + (size_t)b * KDIM * LDXV;

    const int tid  = threadIdx.x;
    const int wid  = tid >> 5;
    const int lane = tid & 31;
    const int lq   = lane >> 2;
    const int ls   = lane & 3;
    const int wo   = (wid >> 2) * 64;
    const int wm   = (wid & 3) * 32;

    const int ao  = tid >> 3, ak4 = tid & 7;
    const int bk  = tid >> 5, bm4 = tid & 31;

    float c[4][4][4];
    #pragma unroll
    for (int mt = 0; mt < 4; mt++)
        #pragma unroll
        for (int nt = 0; nt < 4; nt++)
            #pragma unroll
            for (int r = 0; r < 4; r++) c[mt][nt][r] = 0.0f;

    float4 xreg[4];
    #pragma unroll
    for (int q = 0; q < 4; q++)
        xreg[q] = *(const float4*)&X[(size_t)(bk + q * 8) * LDXV + m0 + bm4 * 4];

    for (int kt = 0; kt < KDIM; kt += BKK) {
        if (kt) __syncthreads();
        #pragma unroll
        for (int q = 0; q < 4; q++) {
            float4 v = *(const float4*)&conv_w[(size_t)(o0 + ao + q * 32) * WLD + WOFF + kt + ak4 * 4];
            float* dst = &Asm[(ao + q * 32) * APAD + ak4 * 4];
            dst[0] = tf32rn(v.x); dst[1] = tf32rn(v.y);
            dst[2] = tf32rn(v.z); dst[3] = tf32rn(v.w);
        }
        #pragma unroll
        for (int q = 0; q < 4; q++) {
            float* dst = &Bsm[(bk + q * 8) * BPAD + bm4 * 4];
            dst[0] = tf32rn(xreg[q].x); dst[1] = tf32rn(xreg[q].y);
            dst[2] = tf32rn(xreg[q].z); dst[3] = tf32rn(xreg[q].w);
        }
        __syncthreads();

        if (kt + BKK < KDIM) {
            #pragma unroll
            for (int q = 0; q < 4; q++)
                xreg[q] = *(const float4*)&X[(size_t)(kt + BKK + bk + q * 8) * LDXV + m0 + bm4 * 4];
        }

        #pragma unroll
        for (int kk = 0; kk < BKK; kk += 8) {
            u32 a[4][4], bb[4][2];
            #pragma unroll
            for (int mt = 0; mt < 4; mt++) {
                const float* ap = &Asm[(wo + mt * 16 + lq) * APAD + kk + ls];
                a[mt][0] = __float_as_uint(ap[0]);
                a[mt][1] = __float_as_uint(ap[8 * APAD]);
                a[mt][2] = __float_as_uint(ap[4]);
                a[mt][3] = __float_as_uint(ap[8 * APAD + 4]);
            }
            #pragma unroll
            for (int nt = 0; nt < 4; nt++) {
                const float* bp = &Bsm[(kk + ls) * BPAD + wm + nt * 8 + lq];
                bb[nt][0] = __float_as_uint(bp[0]);
                bb[nt][1] = __float_as_uint(bp[4 * BPAD]);
            }
            #pragma unroll
            for (int mt = 0; mt < 4; mt++)
                #pragma unroll
                for (int nt = 0; nt < 4; nt++) {
                    asm volatile(
                        "mma.sync.aligned.m16n8k8.row.col.f32.tf32.tf32.f32 "
                        "{%0,%1,%2,%3}, {%4,%5,%6,%7}, {%8,%9}, {%0,%1,%2,%3};"
                        : "+f"(c[mt][nt][0]), "+f"(c[mt][nt][1]),
                          "+f"(c[mt][nt][2]), "+f"(c[mt][nt][3])
                        : "r"(a[mt][0]), "r"(a[mt][1]), "r"(a[mt][2]), "r"(a[mt][3]),
                          "r"(bb[nt][0]), "r"(bb[nt][1]));
                }
        }
    }

    #pragma unroll
    for (int mt = 0; mt < 4; mt++) {
        int row = o0 + wo + mt * 16 + lq;
        #pragma unroll
        for (int nt = 0; nt < 4; nt++) {
            int col = m0 + wm + nt * 8 + ls * 2;
            *(float2*)&outp[(size_t)(b * CD + row) * ldc + col] =
                make_float2(c[mt][nt][0], c[mt][nt][1]);
            *(float2*)&outp[(size_t)(b * CD + row + 8) * ldc + col] =
                make_float2(c[mt][nt][2], c[mt][nt][3]);
        }
    }
}

// ---------------- interp add + BN partial stats (shuffle reduction) ------------
__global__ __launch_bounds__(256) void interp_stats_kernel()
{
    __shared__ float zs[SPTS];
    const int o = blockIdx.x, b = blockIdx.y;
    const float4* zin = (const float4*)(g_z + (size_t)(b * CD + o) * SPTS);
    #pragma unroll
    for (int q = 0; q < SPTS / 4 / 256; q++)
        ((float4*)zs)[threadIdx.x + q * 256] = zin[threadIdx.x + q * 256];
    __syncthreads();

    float4* yrow = (float4*)(g_y + (size_t)(b * CD + o) * MPTS);
    const int4*   ki0 = (const int4*)  (g_ki0 + (size_t)b * MPTS);
    const int4*   ki1 = (const int4*)  (g_ki1 + (size_t)b * MPTS);
    const int4*   ki2 = (const int4*)  (g_ki2 + (size_t)b * MPTS);
    const float4* kw0 = (const float4*)(g_kw0 + (size_t)b * MPTS);
    const float4* kw1 = (const float4*)(g_kw1 + (size_t)b * MPTS);
    const float4* kw2 = (const float4*)(g_kw2 + (size_t)b * MPTS);

    float s = 0.0f, s2 = 0.0f;
    #pragma unroll
    for (int q = 0; q < MPTS / 4 / 256; q++) {
        int m4 = threadIdx.x + q * 256;
        int4   a0 = ki0[m4], a1 = ki1[m4], a2 = ki2[m4];
        float4 w0 = kw0[m4], w1 = kw1[m4], w2 = kw2[m4];
        float4 v = yrow[m4];
        v.x += w0.x * zs[a0.x] + w1.x * zs[a1.x] + w2.x * zs[a2.x];
        v.y += w0.y * zs[a0.y] + w1.y * zs[a1.y] + w2.y * zs[a2.y];
        v.z += w0.z * zs[a0.z] + w1.z * zs[a1.z] + w2.z * zs[a2.z];
        v.w += w0.w * zs[a0.w] + w1.w * zs[a1.w] + w2.w * zs[a2.w];
        yrow[m4] = v;
        s  += v.x + v.y + v.z + v.w;
        s2 += v.x * v.x + v.y * v.y + v.z * v.z + v.w * v.w;
    }
    // warp shuffle reduction + one cross-warp step
    #pragma unroll
    for (int off = 16; off > 0; off >>= 1) {
        s  += __shfl_xor_sync(0xFFFFFFFFu, s,  off);
        s2 += __shfl_xor_sync(0xFFFFFFFFu, s2, off);
    }
    __shared__ float ws[8], ws2[8];
    if ((threadIdx.x & 31) == 0) {
        ws [threadIdx.x >> 5] = s;
        ws2[threadIdx.x >> 5] = s2;
    }
    __syncthreads();
    if (threadIdx.x == 0) {
        float t = 0.0f, t2 = 0.0f;
        #pragma unroll
        for (int i = 0; i < 8; i++) { t += ws[i]; t2 += ws2[i]; }
        g_rsum[b * CD + o]  = t;
        g_rsum2[b * CD + o] = t2;
    }
}

// ---------------- normalize + LeakyReLU + idx tail (one row per block) ---------
#define NB_APPLY (BATCH * CD)   // 2048 blocks; each = one (b,o) full row
__global__ __launch_bounds__(256) void bn_apply_kernel(
    const int* __restrict__ dense_idx,
    const float* __restrict__ gamma, const float* __restrict__ beta,
    float* __restrict__ out, int out_size)
{
    if (blockIdx.x < NB_APPLY) {
        const int o = blockIdx.x & (CD - 1);   // block-uniform channel
        float s = 0.0f, s2 = 0.0f;
        #pragma unroll
        for (int b = 0; b < BATCH; b++) { s += g_rsum[b * CD + o]; s2 += g_rsum2[b * CD + o]; }
        const float invn = 1.0f / (float)(BATCH * MPTS);
        float mean = s * invn;
        float var  = s2 * invn - mean * mean;
        float sc = gamma[o] * rsqrtf(var + 1e-5f);
        float bi = beta[o] - mean * sc;

        const size_t base = (size_t)blockIdx.x * (MPTS / 4);
        #pragma unroll
        for (int q = 0; q < 4; q++) {
            size_t i4 = base + q * 256 + threadIdx.x;
            float4 v = ((const float4*)g_y)[i4];
            float t;
            t = v.x * sc + bi; v.x = (t >= 0.0f) ? t : 0.2f * t;
            t = v.y * sc + bi; v.y = (t >= 0.0f) ? t : 0.2f * t;
            t = v.z * sc + bi; v.z = (t >= 0.0f) ? t : 0.2f * t;
            t = v.w * sc + bi; v.w = (t >= 0.0f) ? t : 0.2f * t;
            ((float4*)out)[i4] = v;
        }
    } else {
        int j = (blockIdx.x - NB_APPLY) * 256 + threadIdx.x;
        if (j < BATCH * MPTS && out_size >= BATCH * CD * MPTS + BATCH * MPTS)
            out[(size_t)BATCH * CD * MPTS + j] = (float)dense_idx[j];
    }
}

// ---------------- host launcher -------------------------------------------------
extern "C" void kernel_launch(void* const* d_in, const int* in_sizes, int n_in,
                              void* d_out, int out_size)
{
    const float* dense_data  = (const float*)d_in[0];
    const int*   dense_idx   = (const int*)  d_in[1];
    const float* sparse_data = (const float*)d_in[2];
    const int*   sparse_idx  = (const int*)  d_in[3];
    const float* pcd         = (const float*)d_in[4];
    const float* conv_w      = (const float*)d_in[5];
    const float* bn_gamma    = (const float*)d_in[6];
    const float* bn_beta     = (const float*)d_in[7];
    float* out = (float*)d_out;

    float* d_z; cudaGetSymbolAddress((void**)&d_z, g_z);
    float* d_y; cudaGetSymbolAddress((void**)&d_y, g_y);

    static cudaStream_t s_side = nullptr;
    static cudaEvent_t ev_fork = nullptr, ev_join = nullptr;
    if (!s_side) {
        cudaStreamCreateWithFlags(&s_side, cudaStreamNonBlocking);
        cudaEventCreateWithFlags(&ev_fork, cudaEventDisableTiming);
        cudaEventCreateWithFlags(&ev_join, cudaEventDisableTiming);
    }

    // fork: KNN on side stream, concurrent with the GEMM (independent data)
    cudaEventRecord(ev_fork, 0);
    cudaStreamWaitEvent(s_side, ev_fork, 0);
    knn_kernel<<<dim3(MPTS / 256, BATCH), 256, 0, s_side>>>(pcd, dense_idx, sparse_idx);
    cudaEventRecord(ev_join, s_side);

    // main stream: merged z & y GEMMs
    gemm_mma_all<<<NZBLK + (MPTS / 128) * 2 * BATCH, 256>>>(
        conv_w, dense_data, sparse_data, d_y, d_z);

    // join before interp (needs knn outputs + both GEMMs)
    cudaStreamWaitEvent(0, ev_join, 0);

    // y += knn-interp(z); fused BN partial sums
    interp_stats_kernel<<<dim3(CD, BATCH), 256>>>();

    // normalize + leaky relu -> out (syncless BN finalize), plus dense_idx tail
    int nb_idx = (BATCH * MPTS + 255) / 256;
    bn_apply_kernel<<<NB_APPLY + nb_idx, 256>>>(dense_idx, bn_gamma, bn_beta, out, out_size);
}

// round 14
// speedup vs baseline: 1.2131x; 1.2131x over previous
#include <cuda_runtime.h>

#define BATCH 8
#define CD 256
#define CS 512
#define MPTS 4096
#define SPTS 1024
#define NPTS 4096
#define WLD 768

typedef unsigned int u32;

// ---------------- scratch (device globals) -----------------------------------
__device__ float g_z[BATCH * CD * SPTS];          // W2 @ sparse : [b][o][s]
__device__ float g_y[(size_t)BATCH * CD * MPTS];  // pre-BN y    : [b][o][m]
__device__ int   g_ki0[BATCH * MPTS];
__device__ int   g_ki1[BATCH * MPTS];
__device__ int   g_ki2[BATCH * MPTS];
__device__ float g_kw0[BATCH * MPTS];
__device__ float g_kw1[BATCH * MPTS];
__device__ float g_kw2[BATCH * MPTS];
__device__ float g_rsum[BATCH * CD];
__device__ float g_rsum2[BATCH * CD];

__device__ __forceinline__ float tf32rn(float x) {
    float y;
    asm("cvt.rna.tf32.f32 %0, %1;" : "=f"(y) : "f"(x));
    return y;
}

// ---------------- kernel 1: KNN (exact fp32, bit-matches reference) -----------
__global__ __launch_bounds__(256) void knn_kernel(
    const float* __restrict__ pcd,
    const int* __restrict__ dense_idx,
    const int* __restrict__ sparse_idx)
{
    __shared__ float sx[SPTS], sy[SPTS], sz[SPTS], ss[SPTS];
    const int b = blockIdx.y;
    const float* pb = pcd + (size_t)b * 3 * NPTS;

    for (int s = threadIdx.x; s < SPTS; s += blockDim.x) {
        int si = sparse_idx[b * SPTS + s];
        float x = pb[si], y = pb[NPTS + si], z = pb[2 * NPTS + si];
        ss[s] = __fadd_rn(__fadd_rn(__fmul_rn(x, x), __fmul_rn(y, y)), __fmul_rn(z, z));
        sx[s] = x; sy[s] = y; sz[s] = z;
    }
    __syncthreads();

    const int m = blockIdx.x * blockDim.x + threadIdx.x;
    const int di = dense_idx[b * MPTS + m];
    const float dx = pb[di], dy = pb[NPTS + di], dz = pb[2 * NPTS + di];
    const float dd = __fadd_rn(__fadd_rn(__fmul_rn(dx, dx), __fmul_rn(dy, dy)),
                               __fmul_rn(dz, dz));

    float d0 = 3.4e38f, d1 = 3.4e38f, d2v = 3.4e38f;
    int i0 = 0, i1 = 0, i2 = 0;
    #pragma unroll 4
    for (int s = 0; s < SPTS; s++) {
        float p0 = __fmul_rn(dx, sx[s]);
        float p1 = __fmul_rn(dy, sy[s]);
        float p2 = __fmul_rn(dz, sz[s]);
        float dot = __fadd_rn(__fadd_rn(p0, p1), p2);
        float d2 = __fadd_rn(__fadd_rn(dd, ss[s]), -__fmul_rn(2.0f, dot));
        if (d2 < d0)       { d2v = d1; i2 = i1; d1 = d0; i1 = i0; d0 = d2; i0 = s; }
        else if (d2 < d1)  { d2v = d1; i2 = i1; d1 = d2; i1 = s; }
        else if (d2 < d2v) { d2v = d2; i2 = s; }
    }
    float w0 = __fdiv_rn(1.0f, __fadd_rn(d0,  1e-8f));
    float w1 = __fdiv_rn(1.0f, __fadd_rn(d1,  1e-8f));
    float w2 = __fdiv_rn(1.0f, __fadd_rn(d2v, 1e-8f));
    float sum = __fadd_rn(__fadd_rn(w0, w1), w2);
    int gi = b * MPTS + m;
    g_ki0[gi] = i0; g_ki1[gi] = i1; g_ki2[gi] = i2;
    g_kw0[gi] = __fdiv_rn(w0, sum);
    g_kw1[gi] = __fdiv_rn(w1, sum);
    g_kw2[gi] = __fdiv_rn(w2, sum);
}

// ---------------- merged tf32 mma.sync GEMM (packed-A fragments) ---------------
// A stored permuted: float4 quad (A[r,k], A[r+8,k], A[r,k+4], A[r+8,k+4])
// at Ap4[(g*4+kb)*33 + lq*4 + ls]   (g = row/16, kb = k-slice/8, pitch 33)
#define BKK 32
#define BPAD 136
#define NZBLK 128
#define A4PITCH 33
#define A4_TOT (32 * A4PITCH)       // 1056 float4 = 16896 B

__global__ __launch_bounds__(256, 2) void gemm_mma_all(
    const float* __restrict__ conv_w,
    const float* __restrict__ dense_data,
    const float* __restrict__ sparse_data,
    float* __restrict__ gy, float* __restrict__ gz)
{
    __shared__ float4 Ap4[A4_TOT];
    __shared__ float  Bsm[BKK * BPAD];

    const int flat = blockIdx.x;
    const bool isZ = flat < NZBLK;

    int KDIM, WOFF, LDXV, ldc, mtiles, idx;
    const float* Xbase; float* outp;
    if (isZ) { KDIM = CS; WOFF = CD; LDXV = SPTS; ldc = SPTS; mtiles = 8;
               Xbase = sparse_data; outp = gz; idx = flat; }
    else     { KDIM = CD; WOFF = 0;  LDXV = MPTS; ldc = MPTS; mtiles = 32;
               Xbase = dense_data; outp = gy; idx = flat - NZBLK; }

    const int mtile = idx % mtiles;
    const int otile = (idx / mtiles) & 1;
    const int b     = idx / (mtiles * 2);
    const int m0 = mtile * 128;
    const int o0 = otile * 128;
    const float* X = Xbase + (size_t)b * KDIM * LDXV;

    const int tid  = threadIdx.x;
    const int wid  = tid >> 5;
    const int lane = tid & 31;
    const int lq   = lane >> 2;
    const int ls   = lane & 3;
    const int wo   = (wid >> 2) * 64;
    const int wm   = (wid & 3) * 32;
    const int gbase = wo >> 4;          // 0 or 4

    const int ao  = tid >> 3, ak4 = tid & 7;
    const int bk  = tid >> 5, bm4 = tid & 31;
    // A-scatter constants (per thread)
    const int kb_w   = ak4 >> 1;
    const int comp_h = (ak4 & 1) * 2;   // 0 -> x/y slots, 2 -> z/w slots

    float c[4][4][4];
    #pragma unroll
    for (int mt = 0; mt < 4; mt++)
        #pragma unroll
        for (int nt = 0; nt < 4; nt++)
            #pragma unroll
            for (int r = 0; r < 4; r++) c[mt][nt][r] = 0.0f;

    float4 xreg[4];
    #pragma unroll
    for (int q = 0; q < 4; q++)
        xreg[q] = *(const float4*)&X[(size_t)(bk + q * 8) * LDXV + m0 + bm4 * 4];

    float* Aw = (float*)Ap4;

    for (int kt = 0; kt < KDIM; kt += BKK) {
        if (kt) __syncthreads();
        // A chunk: load + cvt + scatter into packed-quad layout
        #pragma unroll
        for (int q = 0; q < 4; q++) {
            int row = ao + q * 32;
            float4 v = *(const float4*)&conv_w[(size_t)(o0 + row) * WLD + WOFF + kt + ak4 * 4];
            int g    = row >> 4;
            int rr   = row & 15;
            int lqr  = rr & 7;
            int comp = comp_h + (rr >> 3);               // 0..3
            float* dst = Aw + 4 * ((g * 4 + kb_w) * A4PITCH + lqr * 4) + comp;
            dst[0]  = tf32rn(v.x);
            dst[4]  = tf32rn(v.y);
            dst[8]  = tf32rn(v.z);
            dst[12] = tf32rn(v.w);
        }
        // B chunk from prefetch registers
        #pragma unroll
        for (int q = 0; q < 4; q++) {
            float* dst = &Bsm[(bk + q * 8) * BPAD + bm4 * 4];
            dst[0] = tf32rn(xreg[q].x); dst[1] = tf32rn(xreg[q].y);
            dst[2] = tf32rn(xreg[q].z); dst[3] = tf32rn(xreg[q].w);
        }
        __syncthreads();

        if (kt + BKK < KDIM) {
            #pragma unroll
            for (int q = 0; q < 4; q++)
                xreg[q] = *(const float4*)&X[(size_t)(kt + BKK + bk + q * 8) * LDXV + m0 + bm4 * 4];
        }

        #pragma unroll
        for (int kk = 0; kk < BKK; kk += 8) {
            const int kb = kk >> 3;
            u32 a[4][4], bb[4][2];
            #pragma unroll
            for (int mt = 0; mt < 4; mt++) {
                float4 av = Ap4[((gbase + mt) * 4 + kb) * A4PITCH + lq * 4 + ls];
                a[mt][0] = __float_as_uint(av.x);
                a[mt][1] = __float_as_uint(av.y);
                a[mt][2] = __float_as_uint(av.z);
                a[mt][3] = __float_as_uint(av.w);
            }
            #pragma unroll
            for (int nt = 0; nt < 4; nt++) {
                const float* bp = &Bsm[(kk + ls) * BPAD + wm + nt * 8 + lq];
                bb[nt][0] = __float_as_uint(bp[0]);
                bb[nt][1] = __float_as_uint(bp[4 * BPAD]);
            }
            #pragma unroll
            for (int mt = 0; mt < 4; mt++)
                #pragma unroll
                for (int nt = 0; nt < 4; nt++) {
                    asm volatile(
                        "mma.sync.aligned.m16n8k8.row.col.f32.tf32.tf32.f32 "
                        "{%0,%1,%2,%3}, {%4,%5,%6,%7}, {%8,%9}, {%0,%1,%2,%3};"
                        : "+f"(c[mt][nt][0]), "+f"(c[mt][nt][1]),
                          "+f"(c[mt][nt][2]), "+f"(c[mt][nt][3])
                        : "r"(a[mt][0]), "r"(a[mt][1]), "r"(a[mt][2]), "r"(a[mt][3]),
                          "r"(bb[nt][0]), "r"(bb[nt][1]));
                }
        }
    }

    #pragma unroll
    for (int mt = 0; mt < 4; mt++) {
        int row = o0 + wo + mt * 16 + lq;
        #pragma unroll
        for (int nt = 0; nt < 4; nt++) {
            int col = m0 + wm + nt * 8 + ls * 2;
            *(float2*)&outp[(size_t)(b * CD + row) * ldc + col] =
                make_float2(c[mt][nt][0], c[mt][nt][1]);
            *(float2*)&outp[(size_t)(b * CD + row + 8) * ldc + col] =
                make_float2(c[mt][nt][2], c[mt][nt][3]);
        }
    }
}

// ---------------- interp add + BN partial stats (smem z gathers) ---------------
__global__ __launch_bounds__(256) void interp_stats_kernel()
{
    __shared__ float zs[SPTS];
    const int o = blockIdx.x, b = blockIdx.y;
    const float4* zin = (const float4*)(g_z + (size_t)(b * CD + o) * SPTS);
    #pragma unroll
    for (int q = 0; q < SPTS / 4 / 256; q++)
        ((float4*)zs)[threadIdx.x + q * 256] = zin[threadIdx.x + q * 256];
    __syncthreads();

    float4* yrow = (float4*)(g_y + (size_t)(b * CD + o) * MPTS);
    const int4*   ki0 = (const int4*)  (g_ki0 + (size_t)b * MPTS);
    const int4*   ki1 = (const int4*)  (g_ki1 + (size_t)b * MPTS);
    const int4*   ki2 = (const int4*)  (g_ki2 + (size_t)b * MPTS);
    const float4* kw0 = (const float4*)(g_kw0 + (size_t)b * MPTS);
    const float4* kw1 = (const float4*)(g_kw1 + (size_t)b * MPTS);
    const float4* kw2 = (const float4*)(g_kw2 + (size_t)b * MPTS);

    float s = 0.0f, s2 = 0.0f;
    #pragma unroll
    for (int q = 0; q < MPTS / 4 / 256; q++) {
        int m4 = threadIdx.x + q * 256;
        int4   a0 = ki0[m4], a1 = ki1[m4], a2 = ki2[m4];
        float4 w0 = kw0[m4], w1 = kw1[m4], w2 = kw2[m4];
        float4 v = yrow[m4];
        v.x += w0.x * zs[a0.x] + w1.x * zs[a1.x] + w2.x * zs[a2.x];
        v.y += w0.y * zs[a0.y] + w1.y * zs[a1.y] + w2.y * zs[a2.y];
        v.z += w0.z * zs[a0.z] + w1.z * zs[a1.z] + w2.z * zs[a2.z];
        v.w += w0.w * zs[a0.w] + w1.w * zs[a1.w] + w2.w * zs[a2.w];
        yrow[m4] = v;
        s  += v.x + v.y + v.z + v.w;
        s2 += v.x * v.x + v.y * v.y + v.z * v.z + v.w * v.w;
    }
    __shared__ float sh[256], sh2[256];
    sh[threadIdx.x] = s; sh2[threadIdx.x] = s2;
    __syncthreads();
    for (int off = 128; off > 0; off >>= 1) {
        if (threadIdx.x < off) {
            sh[threadIdx.x]  += sh[threadIdx.x + off];
            sh2[threadIdx.x] += sh2[threadIdx.x + off];
        }
        __syncthreads();
    }
    if (threadIdx.x == 0) {
        g_rsum[b * CD + o]  = sh[0];
        g_rsum2[b * CD + o] = sh2[0];
    }
}

// ---------------- normalize + LeakyReLU + idx tail (syncless finalize) ---------
#define NB_APPLY (BATCH * CD * MPTS / 4 / 256)   // 8192 blocks
__global__ __launch_bounds__(256) void bn_apply_kernel(
    const int* __restrict__ dense_idx,
    const float* __restrict__ gamma, const float* __restrict__ beta,
    float* __restrict__ out, int out_size)
{
    if (blockIdx.x < NB_APPLY) {
        const int o = (blockIdx.x >> 2) & (CD - 1);   // block-uniform channel
        float s = 0.0f, s2 = 0.0f;
        #pragma unroll
        for (int b = 0; b < BATCH; b++) { s += g_rsum[b * CD + o]; s2 += g_rsum2[b * CD + o]; }
        const float invn = 1.0f / (float)(BATCH * MPTS);
        float mean = s * invn;
        float var  = s2 * invn - mean * mean;
        float sc = gamma[o] * rsqrtf(var + 1e-5f);
        float bi = beta[o] - mean * sc;

        size_t i4 = (size_t)blockIdx.x * 256 + threadIdx.x;
        float4 v = ((const float4*)g_y)[i4];
        float t;
        t = v.x * sc + bi; v.x = (t >= 0.0f) ? t : 0.2f * t;
        t = v.y * sc + bi; v.y = (t >= 0.0f) ? t : 0.2f * t;
        t = v.z * sc + bi; v.z = (t >= 0.0f) ? t : 0.2f * t;
        t = v.w * sc + bi; v.w = (t >= 0.0f) ? t : 0.2f * t;
        ((float4*)out)[i4] = v;
    } else {
        int j = (blockIdx.x - NB_APPLY) * 256 + threadIdx.x;
        if (j < BATCH * MPTS && out_size >= BATCH * CD * MPTS + BATCH * MPTS)
            out[(size_t)BATCH * CD * MPTS + j] = (float)dense_idx[j];
    }
}

// ---------------- host launcher -------------------------------------------------
extern "C" void kernel_launch(void* const* d_in, const int* in_sizes, int n_in,
                              void* d_out, int out_size)
{
    const float* dense_data  = (const float*)d_in[0];
    const int*   dense_idx   = (const int*)  d_in[1];
    const float* sparse_data = (const float*)d_in[2];
    const int*   sparse_idx  = (const int*)  d_in[3];
    const float* pcd         = (const float*)d_in[4];
    const float* conv_w      = (const float*)d_in[5];
    const float* bn_gamma    = (const float*)d_in[6];
    const float* bn_beta     = (const float*)d_in[7];
    float* out = (float*)d_out;

    float* d_z; cudaGetSymbolAddress((void**)&d_z, g_z);
    float* d_y; cudaGetSymbolAddress((void**)&d_y, g_y);

    // 1. KNN (exact fp32)
    knn_kernel<<<dim3(MPTS / 256, BATCH), 256>>>(pcd, dense_idx, sparse_idx);

    // 2+3. merged z & y GEMMs (z tiles first: 2x K-depth)
    gemm_mma_all<<<NZBLK + (MPTS / 128) * 2 * BATCH, 256>>>(
        conv_w, dense_data, sparse_data, d_y, d_z);

    // 4. y += knn-interp(z); fused BN partial sums (smem gathers)
    interp_stats_kernel<<<dim3(CD, BATCH), 256>>>();

    // 5. normalize + leaky relu -> out (syncless BN finalize), plus dense_idx tail
    int nb_idx = (BATCH * MPTS + 255) / 256;
    bn_apply_kernel<<<NB_APPLY + nb_idx, 256>>>(dense_idx, bn_gamma, bn_beta, out, out_size);
}